// round 7
// baseline (speedup 1.0000x reference)
#include <cuda_runtime.h>
#include <math.h>
#include <stdint.h>

#define Bb 2
#define Nn 2048
#define EMB 768
#define NH 12
#define DH 64
#define DEPTH 6
#define FF 3072
#define TOK (Bb * Nn)  // 4096
#define LN_EPS 1e-6f

// ---------------- scratch (static device globals) ---------------------------
__device__ float g_h[TOK * EMB];
__device__ float g_y[TOK * EMB];
__device__ float g_qkv[TOK * 3 * EMB];
__device__ float g_o[TOK * EMB];
__device__ float g_mid[TOK * FF];
// transposed + tf32-rounded weights ([Nout][K], K-major rows)
__device__ float g_wqkv[DEPTH * EMB * 3 * EMB];
__device__ float g_wo[DEPTH * EMB * EMB];
__device__ float g_w1[DEPTH * EMB * FF];
__device__ float g_w2[DEPTH * FF * EMB];

__constant__ float c_slopes[NH] = {
    0.5f, 0.25f, 0.125f, 0.0625f, 0.03125f, 0.015625f, 0.0078125f, 0.00390625f,
    0.70710678118654752f, 0.35355339059327376f, 0.17677669529663688f,
    0.08838834764831844f};

__device__ __forceinline__ float rna_tf32(float x) {
    uint32_t u;
    asm("cvt.rna.tf32.f32 %0, %1;" : "=r"(u) : "f"(x));
    return __uint_as_float(u);
}

__device__ __forceinline__ void cp16(uint32_t dst, const void* src) {
    asm volatile("cp.async.ca.shared.global [%0], [%1], 16;" ::"r"(dst),
                 "l"(src));
}

#define MMA_TF32(d, a, b)                                                     \
    asm volatile(                                                             \
        "mma.sync.aligned.m16n8k8.row.col.f32.tf32.tf32.f32 "                 \
        "{%0,%1,%2,%3},{%4,%5,%6,%7},{%8,%9},{%0,%1,%2,%3};"                  \
        : "+f"(d[0]), "+f"(d[1]), "+f"(d[2]), "+f"(d[3])                      \
        : "r"(a[0]), "r"(a[1]), "r"(a[2]), "r"(a[3]), "r"(b[0]), "r"(b[1]))

#define LDSM_X4(r0, r1, r2, r3, addr)                                        \
    asm volatile(                                                            \
        "ldmatrix.sync.aligned.m8n8.x4.shared.b16 {%0,%1,%2,%3}, [%4];"      \
        : "=r"(r0), "=r"(r1), "=r"(r2), "=r"(r3)                             \
        : "r"(addr))

// ---------------- copy x -> h ------------------------------------------------
__global__ void copy_kernel(const float* __restrict__ x) {
    int i = blockIdx.x * blockDim.x + threadIdx.x;
    if (i < TOK * EMB) g_h[i] = x[i];
}

// ---------------- fused transpose+round of ALL weights (one launch) ---------
#define TQKV (72 * 24 * DEPTH)
#define TWO (24 * 24 * DEPTH)
#define TW1 (96 * 24 * DEPTH)
#define TW2 (24 * 96 * DEPTH)
#define TALL (TQKV + TWO + TW1 + TW2)

__global__ void transpose_round_all(const float* __restrict__ wqkv,
                                    const float* __restrict__ wo,
                                    const float* __restrict__ w1,
                                    const float* __restrict__ w2,
                                    float* __restrict__ pwqkv,
                                    float* __restrict__ pwo,
                                    float* __restrict__ pw1,
                                    float* __restrict__ pw2) {
    __shared__ float tile[32][33];
    int b = blockIdx.x;
    const float* W;
    float* Wt;
    int K, N;
    if (b < TQKV) {
        W = wqkv; Wt = pwqkv; K = EMB; N = 3 * EMB;
    } else if (b < TQKV + TWO) {
        b -= TQKV; W = wo; Wt = pwo; K = EMB; N = EMB;
    } else if (b < TQKV + TWO + TW1) {
        b -= TQKV + TWO; W = w1; Wt = pw1; K = EMB; N = FF;
    } else {
        b -= TQKV + TWO + TW1; W = w2; Wt = pw2; K = FF; N = EMB;
    }
    int ntiles = N / 32, tpl = ntiles * (K / 32);
    int layer = b / tpl, rem = b % tpl;
    int bn = (rem % ntiles) * 32, bk = (rem / ntiles) * 32;
    W += (size_t)layer * K * N;
    Wt += (size_t)layer * K * N;
    int tx = threadIdx.x, ty = threadIdx.y;
#pragma unroll
    for (int i = 0; i < 32; i += 8)
        tile[ty + i][tx] = W[(size_t)(bk + ty + i) * N + bn + tx];
    __syncthreads();
#pragma unroll
    for (int i = 0; i < 32; i += 8)
        Wt[(size_t)(bn + ty + i) * K + bk + tx] = rna_tf32(tile[tx][ty + i]);
}

// ---------------- LayerNorm --------------------------------------------------
__global__ void ln_kernel(const float* __restrict__ in,
                          const float* __restrict__ scale,
                          const float* __restrict__ bias,
                          float* __restrict__ out, int do_rna) {
    int row = blockIdx.x;
    const float* p = in + (size_t)row * EMB;
    float s = 0.f, ss = 0.f;
    for (int i = threadIdx.x; i < EMB; i += 256) {
        float v = p[i];
        s += v;
        ss += v * v;
    }
#pragma unroll
    for (int o = 16; o; o >>= 1) {
        s += __shfl_xor_sync(0xffffffffu, s, o);
        ss += __shfl_xor_sync(0xffffffffu, ss, o);
    }
    __shared__ float sh_s[8], sh_ss[8];
    int w = threadIdx.x >> 5, lane = threadIdx.x & 31;
    if (lane == 0) { sh_s[w] = s; sh_ss[w] = ss; }
    __syncthreads();
    if (threadIdx.x < 32) {
        s = (lane < 8) ? sh_s[lane] : 0.f;
        ss = (lane < 8) ? sh_ss[lane] : 0.f;
#pragma unroll
        for (int o = 4; o; o >>= 1) {
            s += __shfl_xor_sync(0xffffffffu, s, o);
            ss += __shfl_xor_sync(0xffffffffu, ss, o);
        }
        if (lane == 0) { sh_s[0] = s; sh_ss[0] = ss; }
    }
    __syncthreads();
    float mean = sh_s[0] * (1.0f / EMB);
    float var = sh_ss[0] * (1.0f / EMB) - mean * mean;
    float inv = rsqrtf(var + LN_EPS);
    float* q = out + (size_t)row * EMB;
    for (int i = threadIdx.x; i < EMB; i += 256) {
        float v = (p[i] - mean) * inv * scale[i] + bias[i];
        q[i] = do_rna ? rna_tf32(v) : v;
    }
}

// ---------------- tf32 mma.sync GEMM: CTA 128x64, 4 warps, 3 CTA/SM ---------
// C[M,Nout] = A[M,K] @ Wt[Nout,K]^T  (+bias, +gelu, +rna, +=C)
#define FLAG_BIAS 1
#define FLAG_GELU 2
#define FLAG_ADD 4
#define FLAG_RNA 8

#define STAGES 3
#define A_STAGE 16384                 // 128 rows x 128B
#define B_STAGE 8192                  // 64 rows x 128B
#define STAGE_BYTES (A_STAGE + B_STAGE)
#define GEMM_SMEM (STAGES * STAGE_BYTES)

__device__ __forceinline__ float gelu_tanh(float x) {
    const float k0 = 0.7978845608028654f;
    return 0.5f * x * (1.0f + tanhf(k0 * (x + 0.044715f * x * x * x)));
}

__global__ __launch_bounds__(128, 3) void gemm_tc(
    const float* __restrict__ A, const float* __restrict__ Wt,
    const float* __restrict__ bias, float* __restrict__ C, int K, int Nout,
    int flags) {
    extern __shared__ char smem[];
    const uint32_t sb = (uint32_t)__cvta_generic_to_shared(smem);
    const int tid = threadIdx.x;
    const int warp = tid >> 5, lane = tid & 31;
    const int wm = warp >> 1, wn = warp & 1;  // 2m x 2n warps
    const int bm = blockIdx.y * 128, bn = blockIdx.x * 64;

    // ---- staging: A row `tid` (8 x 16B); B row tid>>1, half (tid&1) -------
    const float* gA = A + (size_t)(bm + tid) * K;
    const int brow = tid >> 1, bhalf = (tid & 1) * 4;
    const float* gB = Wt + (size_t)(bn + brow) * K + bhalf * 4;
    uint32_t stA[8], stB[4];
#pragma unroll
    for (int c = 0; c < 8; c++)
        stA[c] = sb + (uint32_t)tid * 128 + (((uint32_t)(c ^ (tid & 7))) << 4);
#pragma unroll
    for (int i = 0; i < 4; i++) {
        int c = bhalf + i;
        stB[i] = sb + A_STAGE + (uint32_t)brow * 128 +
                 (((uint32_t)(c ^ (brow & 7))) << 4);
    }

#define LOAD_STAGE(s, t_)                                                  \
    do {                                                                   \
        const float* _a = gA + (t_) * 32;                                  \
        const float* _b = gB + (t_) * 32;                                  \
        uint32_t _so = (uint32_t)(s)*STAGE_BYTES;                          \
        _Pragma("unroll") for (int _c = 0; _c < 8; _c++)                   \
            cp16(stA[_c] + _so, _a + _c * 4);                              \
        _Pragma("unroll") for (int _i = 0; _i < 4; _i++)                   \
            cp16(stB[_i] + _so, _b + _i * 4);                              \
        asm volatile("cp.async.commit_group;");                            \
    } while (0)

    // ---- A fragment addresses (validated R5 scheme) ------------------------
    int aphase = lane >> 3;
    int arow7 = lane & 7;
    int arowadd = (aphase & 1) * 8;
    int acbit = aphase >> 1;
    uint32_t aAddr[4];
#pragma unroll
    for (int mf = 0; mf < 4; mf++) {
        int r = wm * 64 + mf * 16 + arow7 + arowadd;
        aAddr[mf] = sb + (uint32_t)r * 128;
    }
    uint32_t aswz[4];
#pragma unroll
    for (int ks = 0; ks < 4; ks++)
        aswz[ks] = ((uint32_t)((2 * ks + acbit) ^ arow7)) << 4;

    // ---- B fragment addresses: x4 covers 2 n-frags (16 rows) --------------
    // lane group g = lane>>3: matrix g -> rows (g>>1)*8, chunk parity g&1
    int bg = lane >> 3;
    int brow7 = lane & 7;
    int bcbit = bg & 1;
    int brofs = (bg >> 1) * 8;
    uint32_t bAddr[2];  // p=0: n-frags 0,1 ; p=1: n-frags 2,3
#pragma unroll
    for (int p = 0; p < 2; p++) {
        int r = wn * 32 + p * 16 + brofs + brow7;
        bAddr[p] = sb + A_STAGE + (uint32_t)r * 128;
    }
    uint32_t bswz[4];
#pragma unroll
    for (int ks = 0; ks < 4; ks++)
        bswz[ks] = ((uint32_t)((2 * ks + bcbit) ^ brow7)) << 4;

    float acc[4][4][4];
#pragma unroll
    for (int i = 0; i < 4; i++)
#pragma unroll
        for (int j = 0; j < 4; j++)
#pragma unroll
            for (int c = 0; c < 4; c++) acc[i][j][c] = 0.f;

    const int T = K / 32;

    LOAD_STAGE(0, 0);
    LOAD_STAGE(1, 1);

    int s = 0;
    for (int t = 0; t < T; t++) {
        if (t + 1 < T)
            asm volatile("cp.async.wait_group 1;");
        else
            asm volatile("cp.async.wait_group 0;");
        __syncthreads();
        if (t + 2 < T) LOAD_STAGE((s + 2) % STAGES, t + 2);

        uint32_t so = (uint32_t)s * STAGE_BYTES;
#pragma unroll
        for (int ks = 0; ks < 4; ks++) {
            uint32_t af[4][4], bf[4][2];
#pragma unroll
            for (int mf = 0; mf < 4; mf++)
                LDSM_X4(af[mf][0], af[mf][1], af[mf][2], af[mf][3],
                        aAddr[mf] + so + aswz[ks]);
#pragma unroll
            for (int p = 0; p < 2; p++)
                LDSM_X4(bf[2 * p][0], bf[2 * p][1], bf[2 * p + 1][0],
                        bf[2 * p + 1][1], bAddr[p] + so + bswz[ks]);
#pragma unroll
            for (int mf = 0; mf < 4; mf++)
#pragma unroll
                for (int nf = 0; nf < 4; nf++)
                    MMA_TF32(acc[mf][nf], af[mf], bf[nf]);
        }
        s = (s + 1) % STAGES;
    }

    // ---- epilogue ----
    int r = lane >> 2, kq = lane & 3;
#pragma unroll
    for (int mf = 0; mf < 4; mf++) {
#pragma unroll
        for (int nf = 0; nf < 4; nf++) {
            int n0 = bn + wn * 32 + nf * 8 + kq * 2;
#pragma unroll
            for (int half = 0; half < 2; half++) {
                int m0 = bm + wm * 64 + mf * 16 + r + half * 8;
                float2 v;
                v.x = acc[mf][nf][half * 2 + 0];
                v.y = acc[mf][nf][half * 2 + 1];
                if (flags & FLAG_BIAS) {
                    v.x += bias[n0];
                    v.y += bias[n0 + 1];
                }
                if (flags & FLAG_GELU) {
                    v.x = gelu_tanh(v.x);
                    v.y = gelu_tanh(v.y);
                }
                if (flags & FLAG_RNA) {
                    v.x = rna_tf32(v.x);
                    v.y = rna_tf32(v.y);
                }
                float2* dst = (float2*)&C[(size_t)m0 * Nout + n0];
                if (flags & FLAG_ADD) {
                    float2 old = *dst;
                    v.x += old.x;
                    v.y += old.y;
                }
                *dst = v;
            }
        }
    }
}

// ---------------- flash attention (causal + ALiBi) ---------------------------
__global__ __launch_bounds__(128) void attn_kernel(
    const float* __restrict__ qkv, float* __restrict__ out) {
    __shared__ float Qs[64][65];
    __shared__ float Ks[32][65];
    __shared__ float Vs[32][65];
    __shared__ float Ss[64][33];

    int qt = blockIdx.x;
    int bh = blockIdx.y;
    int b = bh / NH, h = bh % NH;
    int t = threadIdx.x;
    int q = t >> 1;
    int half = t & 1;
    int dstart = half * 32;
    int nq = qt * 64 + q;
    float slope = c_slopes[h];
    const float scale = 0.125f;

    for (int i = 0; i < 32; i++) {
        int idx = t + i * 128;
        int row = idx >> 6, d = idx & 63;
        Qs[row][d] =
            qkv[((size_t)(b * Nn + qt * 64 + row) * (3 * EMB)) + h * DH + d] *
            scale;
    }

    float m = -1e30f, l = 0.f;
    float acc[32];
#pragma unroll
    for (int d = 0; d < 32; d++) acc[d] = 0.f;

    int kt_end = 2 * qt + 1;
    for (int kt = 0; kt <= kt_end; kt++) {
        __syncthreads();
        for (int i = 0; i < 16; i++) {
            int idx = t + i * 128;
            int row = idx >> 6, d = idx & 63;
            size_t base =
                (size_t)(b * Nn + kt * 32 + row) * (3 * EMB) + h * DH + d;
            Ks[row][d] = qkv[base + EMB];
            Vs[row][d] = qkv[base + 2 * EMB];
        }
        __syncthreads();

        for (int jj = 0; jj < 16; jj++) {
            int j = half * 16 + jj;
            int nk = kt * 32 + j;
            float s;
            if (nk > nq) {
                s = -1e30f;
            } else {
                s = 0.f;
#pragma unroll
                for (int d = 0; d < 64; d++) s = fmaf(Qs[q][d], Ks[j][d], s);
                s += slope * (float)nk;
            }
            Ss[q][j] = s;
        }
        __syncthreads();

        float tmax = -1e30f;
#pragma unroll
        for (int j = 0; j < 32; j++) tmax = fmaxf(tmax, Ss[q][j]);
        float newm = fmaxf(m, tmax);
        float corr = expf(m - newm);
        m = newm;
        l *= corr;
#pragma unroll
        for (int d = 0; d < 32; d++) acc[d] *= corr;
        for (int j = 0; j < 32; j++) {
            float p = expf(Ss[q][j] - newm);
            l += p;
#pragma unroll
            for (int d = 0; d < 32; d++)
                acc[d] = fmaf(p, Vs[j][dstart + d], acc[d]);
        }
    }

    float invl = 1.0f / l;
    float* op = out + (size_t)(b * Nn + nq) * EMB + h * DH + dstart;
#pragma unroll
    for (int d = 0; d < 32; d++) op[d] = rna_tf32(acc[d] * invl);
}

// ---------------- host orchestration -----------------------------------------
extern "C" void kernel_launch(void* const* d_in, const int* in_sizes, int n_in,
                              void* d_out, int out_size) {
    const float* x = (const float*)d_in[0];
    const float* wqkv = (const float*)d_in[1];
    const float* bqkv = (const float*)d_in[2];
    const float* wo = (const float*)d_in[3];
    const float* bo = (const float*)d_in[4];
    const float* ln1s = (const float*)d_in[5];
    const float* ln1b = (const float*)d_in[6];
    const float* ln2s = (const float*)d_in[7];
    const float* ln2b = (const float*)d_in[8];
    const float* w1 = (const float*)d_in[9];
    const float* w2 = (const float*)d_in[10];
    const float* lnfs = (const float*)d_in[11];
    const float* lnfb = (const float*)d_in[12];
    float* out = (float*)d_out;

    float *p_h, *p_y, *p_qkv, *p_o, *p_mid;
    float *p_wqkv, *p_wo, *p_w1, *p_w2;
    cudaGetSymbolAddress((void**)&p_h, g_h);
    cudaGetSymbolAddress((void**)&p_y, g_y);
    cudaGetSymbolAddress((void**)&p_qkv, g_qkv);
    cudaGetSymbolAddress((void**)&p_o, g_o);
    cudaGetSymbolAddress((void**)&p_mid, g_mid);
    cudaGetSymbolAddress((void**)&p_wqkv, g_wqkv);
    cudaGetSymbolAddress((void**)&p_wo, g_wo);
    cudaGetSymbolAddress((void**)&p_w1, g_w1);
    cudaGetSymbolAddress((void**)&p_w2, g_w2);

    cudaFuncSetAttribute(gemm_tc, cudaFuncAttributeMaxDynamicSharedMemorySize,
                         GEMM_SMEM);

    copy_kernel<<<(TOK * EMB + 255) / 256, 256>>>(x);  // launch 0

    transpose_round_all<<<TALL, dim3(32, 8)>>>(wqkv, wo, w1, w2, p_wqkv, p_wo,
                                               p_w1, p_w2);  // launch 1

    for (int L = 0; L < DEPTH; L++) {
        ln_kernel<<<TOK, 256>>>(p_h, ln1s + L * EMB, ln1b + L * EMB, p_y, 1);
        {  // qkv
            dim3 grid(3 * EMB / 64, TOK / 128);
            gemm_tc<<<grid, 128, GEMM_SMEM>>>(
                p_y, p_wqkv + (size_t)L * EMB * 3 * EMB, bqkv + L * 3 * EMB,
                p_qkv, EMB, 3 * EMB, FLAG_BIAS);
        }
        {
            dim3 grid(Nn / 64, Bb * NH);
            attn_kernel<<<grid, 128>>>(p_qkv, p_o);
        }
        {  // wo  (launch 5 in layer 0 — profiled)
            dim3 grid(EMB / 64, TOK / 128);
            gemm_tc<<<grid, 128, GEMM_SMEM>>>(p_o, p_wo + (size_t)L * EMB * EMB,
                                              bo + L * EMB, p_h, EMB, EMB,
                                              FLAG_BIAS | FLAG_ADD);
        }
        ln_kernel<<<TOK, 256>>>(p_h, ln2s + L * EMB, ln2b + L * EMB, p_y, 1);
        {  // w1 + gelu
            dim3 grid(FF / 64, TOK / 128);
            gemm_tc<<<grid, 128, GEMM_SMEM>>>(p_y, p_w1 + (size_t)L * EMB * FF,
                                              nullptr, p_mid, EMB, FF,
                                              FLAG_GELU | FLAG_RNA);
        }
        {  // w2
            dim3 grid(EMB / 64, TOK / 128);
            gemm_tc<<<grid, 128, GEMM_SMEM>>>(p_mid,
                                              p_w2 + (size_t)L * FF * EMB,
                                              nullptr, p_h, FF, EMB, FLAG_ADD);
        }
    }

    ln_kernel<<<TOK, 256>>>(p_h, lnfs, lnfb, out, 0);
}

// round 8
// speedup vs baseline: 1.1821x; 1.1821x over previous
#include <cuda_runtime.h>
#include <cuda_fp16.h>
#include <math.h>
#include <stdint.h>

#define Bb 2
#define Nn 2048
#define EMB 768
#define NH 12
#define DH 64
#define DEPTH 6
#define FF 3072
#define TOK (Bb * Nn)  // 4096
#define LN_EPS 1e-6f

// ---------------- scratch (static device globals) ---------------------------
__device__ float g_h[TOK * EMB];          // residual stream (fp32)
__device__ __half g_y[TOK * EMB];         // LN output (fp16)
__device__ float g_qkv[TOK * 3 * EMB];    // qkv (fp32, attention input)
__device__ __half g_o[TOK * EMB];         // attention output (fp16)
__device__ __half g_mid[TOK * FF];        // FFN hidden (fp16)
// transposed + fp16 weights ([Nout][K], K-major rows)
__device__ __half g_wqkv[DEPTH * EMB * 3 * EMB];
__device__ __half g_wo[DEPTH * EMB * EMB];
__device__ __half g_w1[DEPTH * EMB * FF];
__device__ __half g_w2[DEPTH * FF * EMB];

__constant__ float c_slopes[NH] = {
    0.5f, 0.25f, 0.125f, 0.0625f, 0.03125f, 0.015625f, 0.0078125f, 0.00390625f,
    0.70710678118654752f, 0.35355339059327376f, 0.17677669529663688f,
    0.08838834764831844f};

__device__ __forceinline__ void cp16(uint32_t dst, const void* src) {
    asm volatile("cp.async.ca.shared.global [%0], [%1], 16;" ::"r"(dst),
                 "l"(src));
}

#define MMA_FP16(d, a, b)                                                     \
    asm volatile(                                                             \
        "mma.sync.aligned.m16n8k16.row.col.f32.f16.f16.f32 "                  \
        "{%0,%1,%2,%3},{%4,%5,%6,%7},{%8,%9},{%0,%1,%2,%3};"                  \
        : "+f"(d[0]), "+f"(d[1]), "+f"(d[2]), "+f"(d[3])                      \
        : "r"(a[0]), "r"(a[1]), "r"(a[2]), "r"(a[3]), "r"(b[0]), "r"(b[1]))

#define LDSM_X4(r0, r1, r2, r3, addr)                                        \
    asm volatile(                                                            \
        "ldmatrix.sync.aligned.m8n8.x4.shared.b16 {%0,%1,%2,%3}, [%4];"      \
        : "=r"(r0), "=r"(r1), "=r"(r2), "=r"(r3)                             \
        : "r"(addr))

// ---------------- copy x -> h ------------------------------------------------
__global__ void copy_kernel(const float* __restrict__ x) {
    int i = blockIdx.x * blockDim.x + threadIdx.x;
    if (i < TOK * EMB) g_h[i] = x[i];
}

// ---------------- fused transpose + fp16 convert of ALL weights -------------
#define TQKV (72 * 24 * DEPTH)
#define TWO (24 * 24 * DEPTH)
#define TW1 (96 * 24 * DEPTH)
#define TW2 (24 * 96 * DEPTH)
#define TALL (TQKV + TWO + TW1 + TW2)

__global__ void transpose_half_all(const float* __restrict__ wqkv,
                                   const float* __restrict__ wo,
                                   const float* __restrict__ w1,
                                   const float* __restrict__ w2,
                                   __half* __restrict__ pwqkv,
                                   __half* __restrict__ pwo,
                                   __half* __restrict__ pw1,
                                   __half* __restrict__ pw2) {
    __shared__ float tile[32][33];
    int b = blockIdx.x;
    const float* W;
    __half* Wt;
    int K, N;
    if (b < TQKV) {
        W = wqkv; Wt = pwqkv; K = EMB; N = 3 * EMB;
    } else if (b < TQKV + TWO) {
        b -= TQKV; W = wo; Wt = pwo; K = EMB; N = EMB;
    } else if (b < TQKV + TWO + TW1) {
        b -= TQKV + TWO; W = w1; Wt = pw1; K = EMB; N = FF;
    } else {
        b -= TQKV + TWO + TW1; W = w2; Wt = pw2; K = FF; N = EMB;
    }
    int ntiles = N / 32, tpl = ntiles * (K / 32);
    int layer = b / tpl, rem = b % tpl;
    int bn = (rem % ntiles) * 32, bk = (rem / ntiles) * 32;
    W += (size_t)layer * K * N;
    Wt += (size_t)layer * K * N;
    int tx = threadIdx.x, ty = threadIdx.y;
#pragma unroll
    for (int i = 0; i < 32; i += 8)
        tile[ty + i][tx] = W[(size_t)(bk + ty + i) * N + bn + tx];
    __syncthreads();
#pragma unroll
    for (int i = 0; i < 32; i += 8)
        Wt[(size_t)(bn + ty + i) * K + bk + tx] =
            __float2half_rn(tile[tx][ty + i]);
}

// ---------------- LayerNorm (float in; float or half out) -------------------
__global__ void ln_kernel(const float* __restrict__ in,
                          const float* __restrict__ scale,
                          const float* __restrict__ bias, void* __restrict__ o,
                          int half_out) {
    int row = blockIdx.x;
    const float* p = in + (size_t)row * EMB;
    float s = 0.f, ss = 0.f;
    for (int i = threadIdx.x; i < EMB; i += 256) {
        float v = p[i];
        s += v;
        ss += v * v;
    }
#pragma unroll
    for (int of = 16; of; of >>= 1) {
        s += __shfl_xor_sync(0xffffffffu, s, of);
        ss += __shfl_xor_sync(0xffffffffu, ss, of);
    }
    __shared__ float sh_s[8], sh_ss[8];
    int w = threadIdx.x >> 5, lane = threadIdx.x & 31;
    if (lane == 0) { sh_s[w] = s; sh_ss[w] = ss; }
    __syncthreads();
    if (threadIdx.x < 32) {
        s = (lane < 8) ? sh_s[lane] : 0.f;
        ss = (lane < 8) ? sh_ss[lane] : 0.f;
#pragma unroll
        for (int of = 4; of; of >>= 1) {
            s += __shfl_xor_sync(0xffffffffu, s, of);
            ss += __shfl_xor_sync(0xffffffffu, ss, of);
        }
        if (lane == 0) { sh_s[0] = s; sh_ss[0] = ss; }
    }
    __syncthreads();
    float mean = sh_s[0] * (1.0f / EMB);
    float var = sh_ss[0] * (1.0f / EMB) - mean * mean;
    float inv = rsqrtf(var + LN_EPS);
    if (half_out) {
        __half* q = (__half*)o + (size_t)row * EMB;
        for (int i = threadIdx.x; i < EMB; i += 256)
            q[i] = __float2half_rn((p[i] - mean) * inv * scale[i] + bias[i]);
    } else {
        float* q = (float*)o + (size_t)row * EMB;
        for (int i = threadIdx.x; i < EMB; i += 256)
            q[i] = (p[i] - mean) * inv * scale[i] + bias[i];
    }
}

// ---------------- fp16 mma.sync GEMM: CTA 128x64, 4 warps, 4 CTA/SM ---------
// C[M,Nout] = A[M,K] @ Wt[Nout,K]^T  (+bias, +gelu, +=C, half-out)
#define FLAG_BIAS 1
#define FLAG_GELU 2
#define FLAG_ADD 4
#define FLAG_HALF 8

#define STAGES 4
#define A_STAGE 8192                // 128 rows x 64B
#define B_STAGE 4096                // 64 rows x 64B
#define STAGE_BYTES (A_STAGE + B_STAGE)
#define GEMM_SMEM (STAGES * STAGE_BYTES)

__device__ __forceinline__ float gelu_tanh(float x) {
    const float k0 = 0.7978845608028654f;
    return 0.5f * x * (1.0f + tanhf(k0 * (x + 0.044715f * x * x * x)));
}

__global__ __launch_bounds__(128, 4) void gemm_fp16(
    const __half* __restrict__ A, const __half* __restrict__ Wt,
    const float* __restrict__ bias, void* __restrict__ Cv, int K, int Nout,
    int flags) {
    extern __shared__ char smem[];
    const uint32_t sb = (uint32_t)__cvta_generic_to_shared(smem);
    const int tid = threadIdx.x;
    const int warp = tid >> 5, lane = tid & 31;
    const int wm = warp >> 1, wn = warp & 1;  // 2m x 2n warps
    const int bm = blockIdx.y * 128, bn = blockIdx.x * 64;

    // ---- staging: A row `tid` (4 x 16B); B row tid>>1, half (tid&1) -------
    const __half* gA = A + (size_t)(bm + tid) * K;
    const int brow = tid >> 1, bc0 = (tid & 1) * 2;
    const __half* gB = Wt + (size_t)(bn + brow) * K + bc0 * 8;
    uint32_t stA[4], stB[2];
#pragma unroll
    for (int c = 0; c < 4; c++)
        stA[c] = sb + (uint32_t)tid * 64 +
                 (((uint32_t)(c ^ ((tid >> 1) & 3))) << 4);
#pragma unroll
    for (int i = 0; i < 2; i++)
        stB[i] = sb + A_STAGE + (uint32_t)brow * 64 +
                 (((uint32_t)((bc0 + i) ^ ((brow >> 1) & 3))) << 4);

#define LOAD_STAGE(s, t_)                                                  \
    do {                                                                   \
        const __half* _a = gA + (t_) * 32;                                 \
        const __half* _b = gB + (t_) * 32;                                 \
        uint32_t _so = (uint32_t)(s)*STAGE_BYTES;                          \
        _Pragma("unroll") for (int _c = 0; _c < 4; _c++)                   \
            cp16(stA[_c] + _so, _a + _c * 8);                              \
        _Pragma("unroll") for (int _i = 0; _i < 2; _i++)                   \
            cp16(stB[_i] + _so, _b + _i * 8);                              \
        asm volatile("cp.async.commit_group;");                            \
    } while (0)

    // ---- A fragment ldmatrix addresses (m16n8k16, x4) ----------------------
    // lanes 0-7: rows 0-7 chunk lo; 8-15: rows 8-15 chunk lo;
    // lanes 16-23: rows 0-7 chunk hi; 24-31: rows 8-15 chunk hi
    int arow7 = lane & 7;
    int a8 = ((lane >> 3) & 1) * 8;
    int acbit = lane >> 4;
    int axor = (arow7 >> 1) & 3;  // higher row bits don't affect (r>>1)&3
    uint32_t aBase[4];
#pragma unroll
    for (int mf = 0; mf < 4; mf++) {
        int r = wm * 64 + mf * 16 + arow7 + a8;
        aBase[mf] = sb + (uint32_t)r * 64;
    }
    uint32_t aoff[2];
#pragma unroll
    for (int ks = 0; ks < 2; ks++)
        aoff[ks] = ((uint32_t)((2 * ks + acbit) ^ axor)) << 4;

    // ---- B fragment addresses: x4 loads 2 n-frags (b0,b1 each) ------------
    // lanes 0-7: rows n0-7 chunk lo; 8-15: n0-7 chunk hi;
    // lanes 16-23: n8-15 chunk lo; 24-31: n8-15 chunk hi
    int brow7 = lane & 7;
    int bn8 = (lane >> 4) * 8;
    int bcb = (lane >> 3) & 1;
    int bxor = (brow7 >> 1) & 3;
    uint32_t bBase[2];
#pragma unroll
    for (int p = 0; p < 2; p++) {
        int r = wn * 32 + p * 16 + brow7 + bn8;
        bBase[p] = sb + A_STAGE + (uint32_t)r * 64;
    }
    uint32_t boff[2];
#pragma unroll
    for (int ks = 0; ks < 2; ks++)
        boff[ks] = ((uint32_t)((2 * ks + bcb) ^ bxor)) << 4;

    float acc[4][4][4];
#pragma unroll
    for (int i = 0; i < 4; i++)
#pragma unroll
        for (int j = 0; j < 4; j++)
#pragma unroll
            for (int c = 0; c < 4; c++) acc[i][j][c] = 0.f;

    const int T = K / 32;

    LOAD_STAGE(0, 0);
    LOAD_STAGE(1, 1);
    LOAD_STAGE(2, 2);

    for (int t = 0; t < T; t++) {
        int rem = ((t + 2 < T) ? (t + 2) : (T - 1)) - t;
        if (rem == 2)
            asm volatile("cp.async.wait_group 2;");
        else if (rem == 1)
            asm volatile("cp.async.wait_group 1;");
        else
            asm volatile("cp.async.wait_group 0;");
        __syncthreads();
        if (t + 3 < T) LOAD_STAGE((t + 3) & 3, t + 3);

        uint32_t so = (uint32_t)(t & 3) * STAGE_BYTES;
#pragma unroll
        for (int ks = 0; ks < 2; ks++) {
            uint32_t af[4][4], bf[4][2];
#pragma unroll
            for (int mf = 0; mf < 4; mf++)
                LDSM_X4(af[mf][0], af[mf][1], af[mf][2], af[mf][3],
                        aBase[mf] + so + aoff[ks]);
#pragma unroll
            for (int p = 0; p < 2; p++)
                LDSM_X4(bf[2 * p][0], bf[2 * p][1], bf[2 * p + 1][0],
                        bf[2 * p + 1][1], bBase[p] + so + boff[ks]);
#pragma unroll
            for (int mf = 0; mf < 4; mf++)
#pragma unroll
                for (int nf = 0; nf < 4; nf++)
                    MMA_FP16(acc[mf][nf], af[mf], bf[nf]);
        }
    }

    // ---- epilogue ----
    int r = lane >> 2, kq = lane & 3;
#pragma unroll
    for (int mf = 0; mf < 4; mf++) {
#pragma unroll
        for (int nf = 0; nf < 4; nf++) {
            int n0 = bn + wn * 32 + nf * 8 + kq * 2;
#pragma unroll
            for (int half = 0; half < 2; half++) {
                int m0 = bm + wm * 64 + mf * 16 + r + half * 8;
                float2 v;
                v.x = acc[mf][nf][half * 2 + 0];
                v.y = acc[mf][nf][half * 2 + 1];
                if (flags & FLAG_BIAS) {
                    v.x += bias[n0];
                    v.y += bias[n0 + 1];
                }
                if (flags & FLAG_GELU) {
                    v.x = gelu_tanh(v.x);
                    v.y = gelu_tanh(v.y);
                }
                if (flags & FLAG_HALF) {
                    __half2* dst =
                        (__half2*)((__half*)Cv + (size_t)m0 * Nout + n0);
                    *dst = __floats2half2_rn(v.x, v.y);
                } else {
                    float2* dst = (float2*)((float*)Cv + (size_t)m0 * Nout + n0);
                    if (flags & FLAG_ADD) {
                        float2 old = *dst;
                        v.x += old.x;
                        v.y += old.y;
                    }
                    *dst = v;
                }
            }
        }
    }
}

// ---------------- flash attention (causal + ALiBi, fp32, half out) ----------
__global__ __launch_bounds__(128) void attn_kernel(
    const float* __restrict__ qkv, __half* __restrict__ out) {
    __shared__ float Qs[64][65];
    __shared__ float Ks[32][65];
    __shared__ float Vs[32][65];
    __shared__ float Ss[64][33];

    int qt = blockIdx.x;
    int bh = blockIdx.y;
    int b = bh / NH, h = bh % NH;
    int t = threadIdx.x;
    int q = t >> 1;
    int half = t & 1;
    int dstart = half * 32;
    int nq = qt * 64 + q;
    float slope = c_slopes[h];
    const float scale = 0.125f;

    for (int i = 0; i < 32; i++) {
        int idx = t + i * 128;
        int row = idx >> 6, d = idx & 63;
        Qs[row][d] =
            qkv[((size_t)(b * Nn + qt * 64 + row) * (3 * EMB)) + h * DH + d] *
            scale;
    }

    float m = -1e30f, l = 0.f;
    float acc[32];
#pragma unroll
    for (int d = 0; d < 32; d++) acc[d] = 0.f;

    int kt_end = 2 * qt + 1;
    for (int kt = 0; kt <= kt_end; kt++) {
        __syncthreads();
        for (int i = 0; i < 16; i++) {
            int idx = t + i * 128;
            int row = idx >> 6, d = idx & 63;
            size_t base =
                (size_t)(b * Nn + kt * 32 + row) * (3 * EMB) + h * DH + d;
            Ks[row][d] = qkv[base + EMB];
            Vs[row][d] = qkv[base + 2 * EMB];
        }
        __syncthreads();

        for (int jj = 0; jj < 16; jj++) {
            int j = half * 16 + jj;
            int nk = kt * 32 + j;
            float s;
            if (nk > nq) {
                s = -1e30f;
            } else {
                s = 0.f;
#pragma unroll
                for (int d = 0; d < 64; d++) s = fmaf(Qs[q][d], Ks[j][d], s);
                s += slope * (float)nk;
            }
            Ss[q][j] = s;
        }
        __syncthreads();

        float tmax = -1e30f;
#pragma unroll
        for (int j = 0; j < 32; j++) tmax = fmaxf(tmax, Ss[q][j]);
        float newm = fmaxf(m, tmax);
        float corr = expf(m - newm);
        m = newm;
        l *= corr;
#pragma unroll
        for (int d = 0; d < 32; d++) acc[d] *= corr;
        for (int j = 0; j < 32; j++) {
            float p = expf(Ss[q][j] - newm);
            l += p;
#pragma unroll
            for (int d = 0; d < 32; d++)
                acc[d] = fmaf(p, Vs[j][dstart + d], acc[d]);
        }
    }

    float invl = 1.0f / l;
    __half* op = out + (size_t)(b * Nn + nq) * EMB + h * DH + dstart;
#pragma unroll
    for (int d = 0; d < 32; d++) op[d] = __float2half_rn(acc[d] * invl);
}

// ---------------- host orchestration -----------------------------------------
extern "C" void kernel_launch(void* const* d_in, const int* in_sizes, int n_in,
                              void* d_out, int out_size) {
    const float* x = (const float*)d_in[0];
    const float* wqkv = (const float*)d_in[1];
    const float* bqkv = (const float*)d_in[2];
    const float* wo = (const float*)d_in[3];
    const float* bo = (const float*)d_in[4];
    const float* ln1s = (const float*)d_in[5];
    const float* ln1b = (const float*)d_in[6];
    const float* ln2s = (const float*)d_in[7];
    const float* ln2b = (const float*)d_in[8];
    const float* w1 = (const float*)d_in[9];
    const float* w2 = (const float*)d_in[10];
    const float* lnfs = (const float*)d_in[11];
    const float* lnfb = (const float*)d_in[12];
    float* out = (float*)d_out;

    float *p_h, *p_qkv;
    __half *p_y, *p_o, *p_mid, *p_wqkv, *p_wo, *p_w1, *p_w2;
    cudaGetSymbolAddress((void**)&p_h, g_h);
    cudaGetSymbolAddress((void**)&p_y, g_y);
    cudaGetSymbolAddress((void**)&p_qkv, g_qkv);
    cudaGetSymbolAddress((void**)&p_o, g_o);
    cudaGetSymbolAddress((void**)&p_mid, g_mid);
    cudaGetSymbolAddress((void**)&p_wqkv, g_wqkv);
    cudaGetSymbolAddress((void**)&p_wo, g_wo);
    cudaGetSymbolAddress((void**)&p_w1, g_w1);
    cudaGetSymbolAddress((void**)&p_w2, g_w2);

    cudaFuncSetAttribute(gemm_fp16, cudaFuncAttributeMaxDynamicSharedMemorySize,
                         GEMM_SMEM);

    copy_kernel<<<(TOK * EMB + 255) / 256, 256>>>(x);  // launch 0

    transpose_half_all<<<TALL, dim3(32, 8)>>>(wqkv, wo, w1, w2, p_wqkv, p_wo,
                                              p_w1, p_w2);  // launch 1

    for (int L = 0; L < DEPTH; L++) {
        ln_kernel<<<TOK, 256>>>(p_h, ln1s + L * EMB, ln1b + L * EMB, p_y, 1);
        {  // qkv = y @ Wqkv + b (fp32 out)
            dim3 grid(3 * EMB / 64, TOK / 128);
            gemm_fp16<<<grid, 128, GEMM_SMEM>>>(
                p_y, p_wqkv + (size_t)L * EMB * 3 * EMB, bqkv + L * 3 * EMB,
                p_qkv, EMB, 3 * EMB, FLAG_BIAS);
        }
        {
            dim3 grid(Nn / 64, Bb * NH);
            attn_kernel<<<grid, 128>>>(p_qkv, p_o);
        }
        {  // h += o @ Wo + bo  (launch 5 in layer 0 — profiled)
            dim3 grid(EMB / 64, TOK / 128);
            gemm_fp16<<<grid, 128, GEMM_SMEM>>>(
                p_o, p_wo + (size_t)L * EMB * EMB, bo + L * EMB, p_h, EMB, EMB,
                FLAG_BIAS | FLAG_ADD);
        }
        ln_kernel<<<TOK, 256>>>(p_h, ln2s + L * EMB, ln2b + L * EMB, p_y, 1);
        {  // mid = gelu(y @ W1) (half out)
            dim3 grid(FF / 64, TOK / 128);
            gemm_fp16<<<grid, 128, GEMM_SMEM>>>(p_y,
                                                p_w1 + (size_t)L * EMB * FF,
                                                nullptr, p_mid, EMB, FF,
                                                FLAG_GELU | FLAG_HALF);
        }
        {  // h += mid @ W2
            dim3 grid(EMB / 64, TOK / 128);
            gemm_fp16<<<grid, 128, GEMM_SMEM>>>(p_mid,
                                                p_w2 + (size_t)L * FF * EMB,
                                                nullptr, p_h, FF, EMB,
                                                FLAG_ADD);
        }
    }

    ln_kernel<<<TOK, 256>>>(p_h, lnfs, lnfb, out, 0);
}